// round 6
// baseline (speedup 1.0000x reference)
#include <cuda_runtime.h>
#include <math.h>

#define Bx 8
#define Nx 1024
#define Cx 64
#define Ox 64
#define Mx 4                 // K+1
#define BN (Bx*Nx)           // 8192
#define BNO (BN*Ox)          // 524288

// ---------------- scratch (device globals; no allocations allowed) ----------
__device__ float g_sRi[BN], g_sIi[BN], g_sRj[BN], g_sIj[BN];
__device__ float g_cmax[BN], g_rsum[BN];
__device__ float g_rowR[Bx*Mx*Nx], g_rowI[Bx*Mx*Nx];
__device__ float g_pR[(size_t)BNO*4], g_pI[(size_t)BNO*4];   // per-m partials, [idx][m]

// ---------------- kernel A: attention projections ---------------------------
__global__ void __launch_bounds__(256) kA(const float* __restrict__ Xr,
                                          const float* __restrict__ Xi,
                                          const float* __restrict__ awr,
                                          const float* __restrict__ awi)
{
    int gw   = (blockIdx.x * blockDim.x + threadIdx.x) >> 5;
    int lane = threadIdx.x & 31;
    if (gw >= BN) return;
    const float* xr = Xr + (size_t)gw * Cx;
    const float* xi = Xi + (size_t)gw * Cx;
    float a1=0.f,a2=0.f,a3=0.f,a4=0.f,a5=0.f,a6=0.f,a7=0.f,a8=0.f;
#pragma unroll
    for (int k = 0; k < 2; k++) {
        int c = lane + (k << 5);
        float xrv = xr[c], xiv = xi[c];
        float wri = awr[c],      wii = awi[c];
        float wrj = awr[Cx + c], wij = awi[Cx + c];
        a1 = fmaf(xrv, wri, a1);  a2 = fmaf(xiv, wii, a2);
        a3 = fmaf(xrv, wii, a3);  a4 = fmaf(xiv, wri, a4);
        a5 = fmaf(xrv, wrj, a5);  a6 = fmaf(xiv, wij, a6);
        a7 = fmaf(xrv, wij, a7);  a8 = fmaf(xiv, wrj, a8);
    }
#pragma unroll
    for (int off = 16; off; off >>= 1) {
        a1 += __shfl_xor_sync(0xffffffffu, a1, off);
        a2 += __shfl_xor_sync(0xffffffffu, a2, off);
        a3 += __shfl_xor_sync(0xffffffffu, a3, off);
        a4 += __shfl_xor_sync(0xffffffffu, a4, off);
        a5 += __shfl_xor_sync(0xffffffffu, a5, off);
        a6 += __shfl_xor_sync(0xffffffffu, a6, off);
        a7 += __shfl_xor_sync(0xffffffffu, a7, off);
        a8 += __shfl_xor_sync(0xffffffffu, a8, off);
    }
    if (lane == 0) {
        g_sRi[gw] = a1 - a2;
        g_sIi[gw] = a3 + a4;
        g_sRj[gw] = a5 - a6;
        g_sIj[gw] = a7 + a8;
    }
}

// ---------------- kernel B: per-(b,j) softmax stats over i ------------------
__global__ void __launch_bounds__(256) kB(const float* __restrict__ br,
                                          const float* __restrict__ bi,
                                          const float* __restrict__ par,
                                          const float* __restrict__ pai)
{
    __shared__ float sri_s[Nx], sii_s[Nx];
    __shared__ float red[8];
    int b  = blockIdx.x >> 8;
    int j0 = (blockIdx.x & 255) << 2;
    float biasr = br[0], biasi = bi[0];
    float apr = par[0], api = pai[0];
    for (int t = threadIdx.x; t < Nx; t += 256) {
        sri_s[t] = g_sRi[b*Nx + t] + biasr;
        sii_s[t] = g_sIi[b*Nx + t] + biasi;
    }
    __syncthreads();
    int lane = threadIdx.x & 31, wid = threadIdx.x >> 5;
    for (int jj = 0; jj < 4; jj++) {
        int j = j0 + jj;
        float sjr = g_sRj[b*Nx + j];
        float sji = g_sIj[b*Nx + j];
        float mags[4];
        float lmax = -1e30f;
#pragma unroll
        for (int k = 0; k < 4; k++) {
            int i = threadIdx.x + (k << 8);
            float scr = sri_s[i] + sjr;
            float sci = sii_s[i] + sji;
            float pr = scr >= 0.f ? scr : apr * scr;
            float pi = sci >= 0.f ? sci : api * sci;
            float s2 = fmaf(pr, pr, pi * pi);
            float rm = rsqrtf(fmaxf(s2, 1e-36f));
            float mg = s2 * rm;
            mags[k] = mg;
            lmax = fmaxf(lmax, mg);
        }
#pragma unroll
        for (int off = 16; off; off >>= 1)
            lmax = fmaxf(lmax, __shfl_xor_sync(0xffffffffu, lmax, off));
        if (lane == 0) red[wid] = lmax;
        __syncthreads();
        float M = red[0];
#pragma unroll
        for (int t = 1; t < 8; t++) M = fmaxf(M, red[t]);
        __syncthreads();
        float ls = 0.f;
#pragma unroll
        for (int k = 0; k < 4; k++) ls += __expf(mags[k] - M);
#pragma unroll
        for (int off = 16; off; off >>= 1)
            ls += __shfl_xor_sync(0xffffffffu, ls, off);
        if (lane == 0) red[wid] = ls;
        __syncthreads();
        if (threadIdx.x == 0) {
            float S = red[0]+red[1]+red[2]+red[3]+red[4]+red[5]+red[6]+red[7];
            g_cmax[b*Nx + j] = M;
            g_rsum[b*Nx + j] = 1.0f / S;
        }
        __syncthreads();
    }
}

// ---------------- kernel C v2: 268 MB L reduction, float4 streams -----------
__global__ void __launch_bounds__(256) kC(const float* __restrict__ Lr,
                                          const float* __restrict__ Li,
                                          const float* __restrict__ br,
                                          const float* __restrict__ bi,
                                          const float* __restrict__ par,
                                          const float* __restrict__ pai)
{
    __shared__ float sjr_s[Nx], sji_s[Nx], cm_s[Nx], rs_s[Nx];
    int b  = blockIdx.x >> 7;
    int i0 = (blockIdx.x & 127) << 3;
    for (int t = threadIdx.x; t < Nx; t += 256) {
        sjr_s[t] = g_sRj[b*Nx + t];
        sji_s[t] = g_sIj[b*Nx + t];
        cm_s[t]  = g_cmax[b*Nx + t];
        rs_s[t]  = g_rsum[b*Nx + t];
    }
    __syncthreads();
    int wid = threadIdx.x >> 5, lane = threadIdx.x & 31;
    int i = i0 + wid;
    float sri = g_sRi[b*Nx + i] + br[0];
    float sii = g_sIi[b*Nx + i] + bi[0];
    float apr = par[0], api = pai[0];
    const size_t MS = (size_t)Nx * Nx;
    const float* pR = Lr + (size_t)b * Mx * MS + (size_t)i * Nx;
    const float* pI = Li + (size_t)b * Mx * MS + (size_t)i * Nx;

    float aR[4] = {0.f,0.f,0.f,0.f};
    float aI[4] = {0.f,0.f,0.f,0.f};

#pragma unroll 1
    for (int jb = 0; jb < Nx; jb += 128) {
        int j0 = jb + (lane << 2);
        float4 R0 = __ldcs((const float4*)(pR          + j0));
        float4 R1 = __ldcs((const float4*)(pR +   MS   + j0));
        float4 R2 = __ldcs((const float4*)(pR + 2*MS   + j0));
        float4 R3 = __ldcs((const float4*)(pR + 3*MS   + j0));
        float4 I0 = __ldcs((const float4*)(pI          + j0));
        float4 I1 = __ldcs((const float4*)(pI +   MS   + j0));
        float4 I2 = __ldcs((const float4*)(pI + 2*MS   + j0));
        float4 I3 = __ldcs((const float4*)(pI + 3*MS   + j0));
        float4 vjr = *(const float4*)&sjr_s[j0];
        float4 vji = *(const float4*)&sji_s[j0];
        float4 vcm = *(const float4*)&cm_s[j0];
        float4 vrs = *(const float4*)&rs_s[j0];

        float ar[4], ai[4];
        const float* jr = (const float*)&vjr;
        const float* ji = (const float*)&vji;
        const float* cm = (const float*)&vcm;
        const float* rs = (const float*)&vrs;
#pragma unroll
        for (int q = 0; q < 4; q++) {
            float scr = sri + jr[q];
            float sci = sii + ji[q];
            float pr = scr >= 0.f ? scr : apr * scr;
            float pi = sci >= 0.f ? sci : api * sci;
            float s2 = fmaf(pr, pr, pi * pi);
            float rm = rsqrtf(fmaxf(s2, 1e-36f));
            float mg = s2 * rm;
            float sc = __fdividef(__expf(mg - cm[q]) * rs[q], mg + 1e-12f);
            ar[q] = sc * pr;
            ai[q] = sc * pi;
        }
        const float* r0 = (const float*)&R0; const float* i0p = (const float*)&I0;
        const float* r1 = (const float*)&R1; const float* i1p = (const float*)&I1;
        const float* r2 = (const float*)&R2; const float* i2p = (const float*)&I2;
        const float* r3 = (const float*)&R3; const float* i3p = (const float*)&I3;
#pragma unroll
        for (int q = 0; q < 4; q++) {
            aR[0] = fmaf(r0[q], ar[q], fmaf(i0p[q], -ai[q], aR[0]));
            aI[0] = fmaf(r0[q], ai[q], fmaf(i0p[q],  ar[q], aI[0]));
            aR[1] = fmaf(r1[q], ar[q], fmaf(i1p[q], -ai[q], aR[1]));
            aI[1] = fmaf(r1[q], ai[q], fmaf(i1p[q],  ar[q], aI[1]));
            aR[2] = fmaf(r2[q], ar[q], fmaf(i2p[q], -ai[q], aR[2]));
            aI[2] = fmaf(r2[q], ai[q], fmaf(i2p[q],  ar[q], aI[2]));
            aR[3] = fmaf(r3[q], ar[q], fmaf(i3p[q], -ai[q], aR[3]));
            aI[3] = fmaf(r3[q], ai[q], fmaf(i3p[q],  ar[q], aI[3]));
        }
    }
#pragma unroll
    for (int off = 16; off; off >>= 1) {
#pragma unroll
        for (int m = 0; m < 4; m++) {
            aR[m] += __shfl_xor_sync(0xffffffffu, aR[m], off);
            aI[m] += __shfl_xor_sync(0xffffffffu, aI[m], off);
        }
    }
    if (lane == 0) {
        size_t o = (size_t)b * Mx * Nx + i;
#pragma unroll
        for (int m = 0; m < 4; m++) {
            g_rowR[o + m*Nx] = aR[m];
            g_rowI[o + m*Nx] = aI[m];
        }
    }
}

// ---------------- kernel D v5: fused output GEMM, 4-way m-split -------------
// grid 1024 = 4 m  x 256 row-tiles. Block: 128 threads, 32 rows x 64 outs,
// per-thread 4x4 tile, single m (no phase loop). 53KB smem -> 4 blocks/SM,
// grid now large enough to reach that limit (16 warps/SM).
// Writes per-m partials to g_pR/g_pI packed [idx][m]; kE combines.
__global__ void __launch_bounds__(128) kD(const float* __restrict__ Xr,
                                          const float* __restrict__ Xi,
                                          const float* __restrict__ wr,
                                          const float* __restrict__ wi)
{
    extern __shared__ __align__(16) float sm[];
    float* Xr_s = sm;                    // [64][36]
    float* Xi_s = sm + 64*36;            // [64][36]
    float* wr_s = sm + 2*64*36;          // [64][68]
    float* wi_s = sm + 2*64*36 + 64*68;  // [64][68]

    int tid  = threadIdx.x;
    int m    = blockIdx.x & 3;
    int tile = blockIdx.x >> 2;
    int r0 = tile << 5;                  // 32 rows per block
    int b  = r0 >> 10;
    int jbase = r0 & 1023;

    // stage X tile transposed + this m's weights concurrently
#pragma unroll
    for (int it = 0; it < 4; it++) {
        int idx = tid + (it << 7);       // 0..511
        int r  = idx >> 4;               // 0..31
        int cg = (idx & 15) << 2;        // 0..60
        float4 v = __ldg((const float4*)(Xr + (size_t)(r0 + r)*64 + cg));
        Xr_s[(cg+0)*36 + r] = v.x;
        Xr_s[(cg+1)*36 + r] = v.y;
        Xr_s[(cg+2)*36 + r] = v.z;
        Xr_s[(cg+3)*36 + r] = v.w;
        float4 u = __ldg((const float4*)(Xi + (size_t)(r0 + r)*64 + cg));
        Xi_s[(cg+0)*36 + r] = u.x;
        Xi_s[(cg+1)*36 + r] = u.y;
        Xi_s[(cg+2)*36 + r] = u.z;
        Xi_s[(cg+3)*36 + r] = u.w;
    }
    {
        const float4* wrg = (const float4*)(wr + (size_t)m * 4096);
        const float4* wig = (const float4*)(wi + (size_t)m * 4096);
#pragma unroll
        for (int k = 0; k < 8; k++) {
            int idx = tid + (k << 7);          // 0..1023
            int c = idx >> 4, og = (idx & 15) << 2;
            *(float4*)&wr_s[c*68 + og] = __ldg(wrg + idx);
            *(float4*)&wi_s[c*68 + og] = __ldg(wig + idx);
        }
    }
    __syncthreads();

    int tx = tid & 15, ty = tid >> 4;    // tx: out-group, ty: row-group
    int oo = tx << 2;
    int rr = ty << 2;

    float cR[4], cI[4];
#pragma unroll
    for (int r = 0; r < 4; r++) {
        size_t o = (size_t)(b*Mx + m)*Nx + jbase + rr + r;
        cR[r] = g_rowR[o];
        cI[r] = g_rowI[o];
    }

    float pR[4][4], pI[4][4];
#pragma unroll
    for (int r = 0; r < 4; r++)
#pragma unroll
        for (int o = 0; o < 4; o++) { pR[r][o] = 0.f; pI[r][o] = 0.f; }

#pragma unroll 4
    for (int c = 0; c < 64; c++) {
        float4 xr4 = *(const float4*)&Xr_s[c*36 + rr];
        float4 xi4 = *(const float4*)&Xi_s[c*36 + rr];
        float4 wv  = *(const float4*)&wr_s[c*68 + oo];
        float4 vv  = *(const float4*)&wi_s[c*68 + oo];
        float xa[4] = {xr4.x, xr4.y, xr4.z, xr4.w};
        float ya[4] = {xi4.x, xi4.y, xi4.z, xi4.w};
        float wa[4] = {wv.x,  wv.y,  wv.z,  wv.w};
        float va[4] = {vv.x,  vv.y,  vv.z,  vv.w};
#pragma unroll
        for (int r = 0; r < 4; r++)
#pragma unroll
            for (int o = 0; o < 4; o++) {
                pR[r][o] = fmaf(xa[r], wa[o], pR[r][o]);
                pI[r][o] = fmaf(ya[r], va[o], pI[r][o]);
            }
    }

    // epilogue: combine with rowR/rowI and store per-m partials
#pragma unroll
    for (int r = 0; r < 4; r++) {
        size_t rowbase = ((size_t)(r0 + rr + r) * 64 + oo) * 4 + m;
#pragma unroll
        for (int o = 0; o < 4; o++) {
            float vr = fmaf(cR[r], pR[r][o], -cI[r] * pI[r][o]);
            float vi = fmaf(cI[r], pR[r][o],  cR[r] * pI[r][o]);
            g_pR[rowbase + (size_t)o*4] = vr;
            g_pI[rowbase + (size_t)o*4] = vi;
        }
    }
}

// ---------------- kernel E: combine 4 m-partials into out -------------------
__global__ void __launch_bounds__(256) kE(float* __restrict__ out)
{
    size_t idx = (size_t)blockIdx.x * 256 + threadIdx.x;   // 0..BNO-1
    float4 a = *(const float4*)&g_pR[idx*4];
    float4 c = *(const float4*)&g_pI[idx*4];
    out[idx]                = (a.x + a.y) + (a.z + a.w);
    out[(size_t)BNO + idx]  = (c.x + c.y) + (c.z + c.w);
}

// ---------------- launch ----------------------------------------------------
extern "C" void kernel_launch(void* const* d_in, const int* in_sizes, int n_in,
                              void* d_out, int out_size)
{
    const float* Xr  = (const float*)d_in[0];
    const float* Xi  = (const float*)d_in[1];
    const float* Lr  = (const float*)d_in[2];
    const float* Li  = (const float*)d_in[3];
    const float* wr  = (const float*)d_in[4];
    const float* wi  = (const float*)d_in[5];
    const float* awr = (const float*)d_in[6];
    const float* awi = (const float*)d_in[7];
    const float* abr = (const float*)d_in[8];
    const float* abi = (const float*)d_in[9];
    const float* par = (const float*)d_in[10];
    const float* pai = (const float*)d_in[11];
    float* out = (float*)d_out;

    const int KD_SMEM = (2*64*36 + 2*64*68) * 4;   // 53248 bytes
    static int attr_done = 0;
    if (!attr_done) {
        cudaFuncSetAttribute(kD, cudaFuncAttributeMaxDynamicSharedMemorySize, KD_SMEM);
        attr_done = 1;
    }

    kA<<<BN/8, 256>>>(Xr, Xi, awr, awi);
    kB<<<Bx*256, 256>>>(abr, abi, par, pai);
    kC<<<Bx*128, 256>>>(Lr, Li, abr, abi, par, pai);
    kD<<<(BN/32)*4, 128, KD_SMEM>>>(Xr, Xi, wr, wi);
    kE<<<BNO/256, 256>>>(out);
}

// round 7
// speedup vs baseline: 1.1063x; 1.1063x over previous
#include <cuda_runtime.h>
#include <math.h>

#define Bx 8
#define Nx 1024
#define Cx 64
#define Ox 64
#define Mx 4                 // K+1
#define BN (Bx*Nx)           // 8192
#define BNO (BN*Ox)          // 524288

// ---------------- scratch (device globals; no allocations allowed) ----------
__device__ float g_sRi[BN], g_sIi[BN], g_sRj[BN], g_sIj[BN];
__device__ float g_cmax[BN], g_rsum[BN];
__device__ float g_rowR[Bx*Mx*Nx], g_rowI[Bx*Mx*Nx];
__device__ float g_pR[(size_t)Mx*BNO], g_pI[(size_t)Mx*BNO];   // partials [m][idx]

// ---------------- kernel A: attention projections ---------------------------
__global__ void __launch_bounds__(256) kA(const float* __restrict__ Xr,
                                          const float* __restrict__ Xi,
                                          const float* __restrict__ awr,
                                          const float* __restrict__ awi)
{
    int gw   = (blockIdx.x * blockDim.x + threadIdx.x) >> 5;
    int lane = threadIdx.x & 31;
    if (gw >= BN) return;
    const float* xr = Xr + (size_t)gw * Cx;
    const float* xi = Xi + (size_t)gw * Cx;
    float a1=0.f,a2=0.f,a3=0.f,a4=0.f,a5=0.f,a6=0.f,a7=0.f,a8=0.f;
#pragma unroll
    for (int k = 0; k < 2; k++) {
        int c = lane + (k << 5);
        float xrv = xr[c], xiv = xi[c];
        float wri = awr[c],      wii = awi[c];
        float wrj = awr[Cx + c], wij = awi[Cx + c];
        a1 = fmaf(xrv, wri, a1);  a2 = fmaf(xiv, wii, a2);
        a3 = fmaf(xrv, wii, a3);  a4 = fmaf(xiv, wri, a4);
        a5 = fmaf(xrv, wrj, a5);  a6 = fmaf(xiv, wij, a6);
        a7 = fmaf(xrv, wij, a7);  a8 = fmaf(xiv, wrj, a8);
    }
#pragma unroll
    for (int off = 16; off; off >>= 1) {
        a1 += __shfl_xor_sync(0xffffffffu, a1, off);
        a2 += __shfl_xor_sync(0xffffffffu, a2, off);
        a3 += __shfl_xor_sync(0xffffffffu, a3, off);
        a4 += __shfl_xor_sync(0xffffffffu, a4, off);
        a5 += __shfl_xor_sync(0xffffffffu, a5, off);
        a6 += __shfl_xor_sync(0xffffffffu, a6, off);
        a7 += __shfl_xor_sync(0xffffffffu, a7, off);
        a8 += __shfl_xor_sync(0xffffffffu, a8, off);
    }
    if (lane == 0) {
        g_sRi[gw] = a1 - a2;
        g_sIi[gw] = a3 + a4;
        g_sRj[gw] = a5 - a6;
        g_sIj[gw] = a7 + a8;
    }
}

// ---------------- kernel B: per-(b,j) softmax stats over i ------------------
__global__ void __launch_bounds__(256) kB(const float* __restrict__ br,
                                          const float* __restrict__ bi,
                                          const float* __restrict__ par,
                                          const float* __restrict__ pai)
{
    __shared__ float sri_s[Nx], sii_s[Nx];
    __shared__ float red[8];
    int b  = blockIdx.x >> 8;
    int j0 = (blockIdx.x & 255) << 2;
    float biasr = br[0], biasi = bi[0];
    float apr = par[0], api = pai[0];
    for (int t = threadIdx.x; t < Nx; t += 256) {
        sri_s[t] = g_sRi[b*Nx + t] + biasr;
        sii_s[t] = g_sIi[b*Nx + t] + biasi;
    }
    __syncthreads();
    int lane = threadIdx.x & 31, wid = threadIdx.x >> 5;
    for (int jj = 0; jj < 4; jj++) {
        int j = j0 + jj;
        float sjr = g_sRj[b*Nx + j];
        float sji = g_sIj[b*Nx + j];
        float mags[4];
        float lmax = -1e30f;
#pragma unroll
        for (int k = 0; k < 4; k++) {
            int i = threadIdx.x + (k << 8);
            float scr = sri_s[i] + sjr;
            float sci = sii_s[i] + sji;
            float pr = scr >= 0.f ? scr : apr * scr;
            float pi = sci >= 0.f ? sci : api * sci;
            float s2 = fmaf(pr, pr, pi * pi);
            float rm = rsqrtf(fmaxf(s2, 1e-36f));
            float mg = s2 * rm;
            mags[k] = mg;
            lmax = fmaxf(lmax, mg);
        }
#pragma unroll
        for (int off = 16; off; off >>= 1)
            lmax = fmaxf(lmax, __shfl_xor_sync(0xffffffffu, lmax, off));
        if (lane == 0) red[wid] = lmax;
        __syncthreads();
        float M = red[0];
#pragma unroll
        for (int t = 1; t < 8; t++) M = fmaxf(M, red[t]);
        __syncthreads();
        float ls = 0.f;
#pragma unroll
        for (int k = 0; k < 4; k++) ls += __expf(mags[k] - M);
#pragma unroll
        for (int off = 16; off; off >>= 1)
            ls += __shfl_xor_sync(0xffffffffu, ls, off);
        if (lane == 0) red[wid] = ls;
        __syncthreads();
        if (threadIdx.x == 0) {
            float S = red[0]+red[1]+red[2]+red[3]+red[4]+red[5]+red[6]+red[7];
            g_cmax[b*Nx + j] = M;
            g_rsum[b*Nx + j] = 1.0f / S;
        }
        __syncthreads();
    }
}

// ---------------- kernel C v3: 268 MB L reduction, 16-deep load batches -----
// grid 8*128 blocks, 8 warps/block, one warp per i-row. j-chunk = 256:
// each lane front-batches 16 LDG.128 (2KB in flight) before the consume chain.
__global__ void __launch_bounds__(256) kC(const float* __restrict__ Lr,
                                          const float* __restrict__ Li,
                                          const float* __restrict__ br,
                                          const float* __restrict__ bi,
                                          const float* __restrict__ par,
                                          const float* __restrict__ pai)
{
    __shared__ float sjr_s[Nx], sji_s[Nx], cm_s[Nx], rs_s[Nx];
    int b  = blockIdx.x >> 7;
    int i0 = (blockIdx.x & 127) << 3;
    for (int t = threadIdx.x; t < Nx; t += 256) {
        sjr_s[t] = g_sRj[b*Nx + t];
        sji_s[t] = g_sIj[b*Nx + t];
        cm_s[t]  = g_cmax[b*Nx + t];
        rs_s[t]  = g_rsum[b*Nx + t];
    }
    __syncthreads();
    int wid = threadIdx.x >> 5, lane = threadIdx.x & 31;
    int i = i0 + wid;
    float sri = g_sRi[b*Nx + i] + br[0];
    float sii = g_sIi[b*Nx + i] + bi[0];
    float apr = par[0], api = pai[0];
    const size_t MS = (size_t)Nx * Nx;
    const float* pR = Lr + (size_t)b * Mx * MS + (size_t)i * Nx;
    const float* pI = Li + (size_t)b * Mx * MS + (size_t)i * Nx;

    float aR[4] = {0.f,0.f,0.f,0.f};
    float aI[4] = {0.f,0.f,0.f,0.f};

#pragma unroll 1
    for (int jb = 0; jb < Nx; jb += 256) {
        int j0 = jb + (lane << 2);        // first half
        int j1 = j0 + 128;                // second half
        // front-batch all 16 stream loads (LDG.128, streaming)
        float4 Ra[4], Ia[4], Rb[4], Ib[4];
#pragma unroll
        for (int m = 0; m < 4; m++) {
            Ra[m] = __ldcs((const float4*)(pR + m*MS + j0));
            Ia[m] = __ldcs((const float4*)(pI + m*MS + j0));
            Rb[m] = __ldcs((const float4*)(pR + m*MS + j1));
            Ib[m] = __ldcs((const float4*)(pI + m*MS + j1));
        }
#pragma unroll
        for (int h = 0; h < 2; h++) {
            int jj = h ? j1 : j0;
            float4 vjr = *(const float4*)&sjr_s[jj];
            float4 vji = *(const float4*)&sji_s[jj];
            float4 vcm = *(const float4*)&cm_s[jj];
            float4 vrs = *(const float4*)&rs_s[jj];
            float ar[4], ai[4];
            const float* jr = (const float*)&vjr;
            const float* ji = (const float*)&vji;
            const float* cm = (const float*)&vcm;
            const float* rs = (const float*)&vrs;
#pragma unroll
            for (int q = 0; q < 4; q++) {
                float scr = sri + jr[q];
                float sci = sii + ji[q];
                float pr = scr >= 0.f ? scr : apr * scr;
                float pi = sci >= 0.f ? sci : api * sci;
                float s2 = fmaf(pr, pr, pi * pi);
                float rm = rsqrtf(fmaxf(s2, 1e-36f));
                float mg = s2 * rm;
                float sc = __fdividef(__expf(mg - cm[q]) * rs[q], mg + 1e-12f);
                ar[q] = sc * pr;
                ai[q] = sc * pi;
            }
#pragma unroll
            for (int m = 0; m < 4; m++) {
                const float* rv = h ? (const float*)&Rb[m] : (const float*)&Ra[m];
                const float* iv = h ? (const float*)&Ib[m] : (const float*)&Ia[m];
#pragma unroll
                for (int q = 0; q < 4; q++) {
                    aR[m] = fmaf(rv[q], ar[q], fmaf(iv[q], -ai[q], aR[m]));
                    aI[m] = fmaf(rv[q], ai[q], fmaf(iv[q],  ar[q], aI[m]));
                }
            }
        }
    }
#pragma unroll
    for (int off = 16; off; off >>= 1) {
#pragma unroll
        for (int m = 0; m < 4; m++) {
            aR[m] += __shfl_xor_sync(0xffffffffu, aR[m], off);
            aI[m] += __shfl_xor_sync(0xffffffffu, aI[m], off);
        }
    }
    if (lane == 0) {
        size_t o = (size_t)b * Mx * Nx + i;
#pragma unroll
        for (int m = 0; m < 4; m++) {
            g_rowR[o + m*Nx] = aR[m];
            g_rowI[o + m*Nx] = aI[m];
        }
    }
}

// ---------------- kernel D v7: m-split GEMM, coalesced partials -------------
// grid 1024 = 4 m x 256 row-tiles. 128 threads, 32 rows x 64 outs, 4x4 tile.
// Partials stored [m][idx] -> warp float4 stores fully coalesced.
__global__ void __launch_bounds__(128) kD(const float* __restrict__ Xr,
                                          const float* __restrict__ Xi,
                                          const float* __restrict__ wr,
                                          const float* __restrict__ wi)
{
    extern __shared__ __align__(16) float sm[];
    float* Xr_s = sm;                    // [64][36]
    float* Xi_s = sm + 64*36;            // [64][36]
    float* wr_s = sm + 2*64*36;          // [64][68]
    float* wi_s = sm + 2*64*36 + 64*68;  // [64][68]

    int tid  = threadIdx.x;
    int m    = blockIdx.x & 3;
    int tile = blockIdx.x >> 2;
    int r0 = tile << 5;                  // 32 rows per block
    int b  = r0 >> 10;
    int jbase = r0 & 1023;

    // stage X tile transposed + this m's weights
#pragma unroll
    for (int it = 0; it < 4; it++) {
        int idx = tid + (it << 7);       // 0..511
        int r  = idx >> 4;               // 0..31
        int cg = (idx & 15) << 2;        // 0..60
        float4 v = __ldg((const float4*)(Xr + (size_t)(r0 + r)*64 + cg));
        Xr_s[(cg+0)*36 + r] = v.x;
        Xr_s[(cg+1)*36 + r] = v.y;
        Xr_s[(cg+2)*36 + r] = v.z;
        Xr_s[(cg+3)*36 + r] = v.w;
        float4 u = __ldg((const float4*)(Xi + (size_t)(r0 + r)*64 + cg));
        Xi_s[(cg+0)*36 + r] = u.x;
        Xi_s[(cg+1)*36 + r] = u.y;
        Xi_s[(cg+2)*36 + r] = u.z;
        Xi_s[(cg+3)*36 + r] = u.w;
    }
    {
        const float4* wrg = (const float4*)(wr + (size_t)m * 4096);
        const float4* wig = (const float4*)(wi + (size_t)m * 4096);
#pragma unroll
        for (int k = 0; k < 8; k++) {
            int idx = tid + (k << 7);          // 0..1023
            int c = idx >> 4, og = (idx & 15) << 2;
            *(float4*)&wr_s[c*68 + og] = __ldg(wrg + idx);
            *(float4*)&wi_s[c*68 + og] = __ldg(wig + idx);
        }
    }
    __syncthreads();

    int tx = tid & 15, ty = tid >> 4;    // tx: out-group, ty: row-group
    int oo = tx << 2;
    int rr = ty << 2;

    float cR[4], cI[4];
#pragma unroll
    for (int r = 0; r < 4; r++) {
        size_t o = (size_t)(b*Mx + m)*Nx + jbase + rr + r;
        cR[r] = g_rowR[o];
        cI[r] = g_rowI[o];
    }

    float pR[4][4], pI[4][4];
#pragma unroll
    for (int r = 0; r < 4; r++)
#pragma unroll
        for (int o = 0; o < 4; o++) { pR[r][o] = 0.f; pI[r][o] = 0.f; }

#pragma unroll 4
    for (int c = 0; c < 64; c++) {
        float4 xr4 = *(const float4*)&Xr_s[c*36 + rr];
        float4 xi4 = *(const float4*)&Xi_s[c*36 + rr];
        float4 wv  = *(const float4*)&wr_s[c*68 + oo];
        float4 vv  = *(const float4*)&wi_s[c*68 + oo];
        float xa[4] = {xr4.x, xr4.y, xr4.z, xr4.w};
        float ya[4] = {xi4.x, xi4.y, xi4.z, xi4.w};
        float wa[4] = {wv.x,  wv.y,  wv.z,  wv.w};
        float va[4] = {vv.x,  vv.y,  vv.z,  vv.w};
#pragma unroll
        for (int r = 0; r < 4; r++)
#pragma unroll
            for (int o = 0; o < 4; o++) {
                pR[r][o] = fmaf(xa[r], wa[o], pR[r][o]);
                pI[r][o] = fmaf(ya[r], va[o], pI[r][o]);
            }
    }

    // epilogue: combine and store coalesced per-m partials
    float* gR = g_pR + (size_t)m * BNO;
    float* gI = g_pI + (size_t)m * BNO;
#pragma unroll
    for (int r = 0; r < 4; r++) {
        size_t idx = (size_t)(r0 + rr + r) * 64 + oo;
        float4 vr, vi;
        vr.x = fmaf(cR[r], pR[r][0], -cI[r] * pI[r][0]);
        vr.y = fmaf(cR[r], pR[r][1], -cI[r] * pI[r][1]);
        vr.z = fmaf(cR[r], pR[r][2], -cI[r] * pI[r][2]);
        vr.w = fmaf(cR[r], pR[r][3], -cI[r] * pI[r][3]);
        vi.x = fmaf(cI[r], pR[r][0],  cR[r] * pI[r][0]);
        vi.y = fmaf(cI[r], pR[r][1],  cR[r] * pI[r][1]);
        vi.z = fmaf(cI[r], pR[r][2],  cR[r] * pI[r][2]);
        vi.w = fmaf(cI[r], pR[r][3],  cR[r] * pI[r][3]);
        *(float4*)(gR + idx) = vr;
        *(float4*)(gI + idx) = vi;
    }
}

// ---------------- kernel E: combine 4 m-partials into out -------------------
// grid 512 x 256: each thread sums one float4 across the 4 m-streams.
__global__ void __launch_bounds__(256) kE(float* __restrict__ out)
{
    size_t idx = ((size_t)blockIdx.x * 256 + threadIdx.x) << 2;   // 0..BNO-1, x4
    float4 r0 = *(const float4*)&g_pR[idx];
    float4 r1 = *(const float4*)&g_pR[(size_t)BNO + idx];
    float4 r2 = *(const float4*)&g_pR[(size_t)2*BNO + idx];
    float4 r3 = *(const float4*)&g_pR[(size_t)3*BNO + idx];
    float4 i0 = *(const float4*)&g_pI[idx];
    float4 i1 = *(const float4*)&g_pI[(size_t)BNO + idx];
    float4 i2 = *(const float4*)&g_pI[(size_t)2*BNO + idx];
    float4 i3 = *(const float4*)&g_pI[(size_t)3*BNO + idx];
    float4 vr, vi;
    vr.x = (r0.x + r1.x) + (r2.x + r3.x);
    vr.y = (r0.y + r1.y) + (r2.y + r3.y);
    vr.z = (r0.z + r1.z) + (r2.z + r3.z);
    vr.w = (r0.w + r1.w) + (r2.w + r3.w);
    vi.x = (i0.x + i1.x) + (i2.x + i3.x);
    vi.y = (i0.y + i1.y) + (i2.y + i3.y);
    vi.z = (i0.z + i1.z) + (i2.z + i3.z);
    vi.w = (i0.w + i1.w) + (i2.w + i3.w);
    *(float4*)(out + idx)               = vr;
    *(float4*)(out + (size_t)BNO + idx) = vi;
}

// ---------------- launch ----------------------------------------------------
extern "C" void kernel_launch(void* const* d_in, const int* in_sizes, int n_in,
                              void* d_out, int out_size)
{
    const float* Xr  = (const float*)d_in[0];
    const float* Xi  = (const float*)d_in[1];
    const float* Lr  = (const float*)d_in[2];
    const float* Li  = (const float*)d_in[3];
    const float* wr  = (const float*)d_in[4];
    const float* wi  = (const float*)d_in[5];
    const float* awr = (const float*)d_in[6];
    const float* awi = (const float*)d_in[7];
    const float* abr = (const float*)d_in[8];
    const float* abi = (const float*)d_in[9];
    const float* par = (const float*)d_in[10];
    const float* pai = (const float*)d_in[11];
    float* out = (float*)d_out;

    const int KD_SMEM = (2*64*36 + 2*64*68) * 4;   // 53248 bytes
    static int attr_done = 0;
    if (!attr_done) {
        cudaFuncSetAttribute(kD, cudaFuncAttributeMaxDynamicSharedMemorySize, KD_SMEM);
        attr_done = 1;
    }

    kA<<<BN/8, 256>>>(Xr, Xi, awr, awi);
    kB<<<Bx*256, 256>>>(abr, abi, par, pai);
    kC<<<Bx*128, 256>>>(Lr, Li, abr, abi, par, pai);
    kD<<<(BN/32)*4, 128, KD_SMEM>>>(Xr, Xi, wr, wi);
    kE<<<BNO/1024, 256>>>(out);
}

// round 9
// speedup vs baseline: 1.1755x; 1.0625x over previous
#include <cuda_runtime.h>
#include <math.h>

#define Bx 8
#define Nx 1024
#define Cx 64
#define Ox 64
#define Mx 4                 // K+1
#define BN (Bx*Nx)           // 8192
#define BNO (BN*Ox)          // 524288

// ---------------- scratch (device globals; no allocations allowed) ----------
__device__ float g_sRi[BN], g_sIi[BN], g_sRj[BN], g_sIj[BN];
__device__ float g_cmax[BN], g_rsum[BN];
__device__ float g_rowR[Bx*Mx*Nx], g_rowI[Bx*Mx*Nx];
__device__ float g_pR[(size_t)Mx*BNO], g_pI[(size_t)Mx*BNO];   // partials [m][idx]

// ---------------- kernel A: attention projections ---------------------------
__global__ void __launch_bounds__(256) kA(const float* __restrict__ Xr,
                                          const float* __restrict__ Xi,
                                          const float* __restrict__ awr,
                                          const float* __restrict__ awi)
{
    int gw   = (blockIdx.x * blockDim.x + threadIdx.x) >> 5;
    int lane = threadIdx.x & 31;
    if (gw >= BN) return;
    const float* xr = Xr + (size_t)gw * Cx;
    const float* xi = Xi + (size_t)gw * Cx;
    float a1=0.f,a2=0.f,a3=0.f,a4=0.f,a5=0.f,a6=0.f,a7=0.f,a8=0.f;
#pragma unroll
    for (int k = 0; k < 2; k++) {
        int c = lane + (k << 5);
        float xrv = xr[c], xiv = xi[c];
        float wri = awr[c],      wii = awi[c];
        float wrj = awr[Cx + c], wij = awi[Cx + c];
        a1 = fmaf(xrv, wri, a1);  a2 = fmaf(xiv, wii, a2);
        a3 = fmaf(xrv, wii, a3);  a4 = fmaf(xiv, wri, a4);
        a5 = fmaf(xrv, wrj, a5);  a6 = fmaf(xiv, wij, a6);
        a7 = fmaf(xrv, wij, a7);  a8 = fmaf(xiv, wrj, a8);
    }
#pragma unroll
    for (int off = 16; off; off >>= 1) {
        a1 += __shfl_xor_sync(0xffffffffu, a1, off);
        a2 += __shfl_xor_sync(0xffffffffu, a2, off);
        a3 += __shfl_xor_sync(0xffffffffu, a3, off);
        a4 += __shfl_xor_sync(0xffffffffu, a4, off);
        a5 += __shfl_xor_sync(0xffffffffu, a5, off);
        a6 += __shfl_xor_sync(0xffffffffu, a6, off);
        a7 += __shfl_xor_sync(0xffffffffu, a7, off);
        a8 += __shfl_xor_sync(0xffffffffu, a8, off);
    }
    if (lane == 0) {
        g_sRi[gw] = a1 - a2;
        g_sIi[gw] = a3 + a4;
        g_sRj[gw] = a5 - a6;
        g_sIj[gw] = a7 + a8;
    }
}

// ---------------- kernel B: per-(b,j) softmax stats over i ------------------
__global__ void __launch_bounds__(256) kB(const float* __restrict__ br,
                                          const float* __restrict__ bi,
                                          const float* __restrict__ par,
                                          const float* __restrict__ pai)
{
    __shared__ float sri_s[Nx], sii_s[Nx];
    __shared__ float red[8];
    int b  = blockIdx.x >> 8;
    int j0 = (blockIdx.x & 255) << 2;
    float biasr = br[0], biasi = bi[0];
    float apr = par[0], api = pai[0];
    for (int t = threadIdx.x; t < Nx; t += 256) {
        sri_s[t] = g_sRi[b*Nx + t] + biasr;
        sii_s[t] = g_sIi[b*Nx + t] + biasi;
    }
    __syncthreads();
    int lane = threadIdx.x & 31, wid = threadIdx.x >> 5;
    for (int jj = 0; jj < 4; jj++) {
        int j = j0 + jj;
        float sjr = g_sRj[b*Nx + j];
        float sji = g_sIj[b*Nx + j];
        float mags[4];
        float lmax = -1e30f;
#pragma unroll
        for (int k = 0; k < 4; k++) {
            int i = threadIdx.x + (k << 8);
            float scr = sri_s[i] + sjr;
            float sci = sii_s[i] + sji;
            float pr = scr >= 0.f ? scr : apr * scr;
            float pi = sci >= 0.f ? sci : api * sci;
            float s2 = fmaf(pr, pr, pi * pi);
            float rm = rsqrtf(fmaxf(s2, 1e-36f));
            float mg = s2 * rm;
            mags[k] = mg;
            lmax = fmaxf(lmax, mg);
        }
#pragma unroll
        for (int off = 16; off; off >>= 1)
            lmax = fmaxf(lmax, __shfl_xor_sync(0xffffffffu, lmax, off));
        if (lane == 0) red[wid] = lmax;
        __syncthreads();
        float M = red[0];
#pragma unroll
        for (int t = 1; t < 8; t++) M = fmaxf(M, red[t]);
        __syncthreads();
        float ls = 0.f;
#pragma unroll
        for (int k = 0; k < 4; k++) ls += __expf(mags[k] - M);
#pragma unroll
        for (int off = 16; off; off >>= 1)
            ls += __shfl_xor_sync(0xffffffffu, ls, off);
        if (lane == 0) red[wid] = ls;
        __syncthreads();
        if (threadIdx.x == 0) {
            float S = red[0]+red[1]+red[2]+red[3]+red[4]+red[5]+red[6]+red[7];
            g_cmax[b*Nx + j] = M;
            g_rsum[b*Nx + j] = 1.0f / S;
        }
        __syncthreads();
    }
}

// ---------------- kernel C v2 (measured best): 128-j chunks, 8 LDG.128 ------
__global__ void __launch_bounds__(256) kC(const float* __restrict__ Lr,
                                          const float* __restrict__ Li,
                                          const float* __restrict__ br,
                                          const float* __restrict__ bi,
                                          const float* __restrict__ par,
                                          const float* __restrict__ pai)
{
    __shared__ float sjr_s[Nx], sji_s[Nx], cm_s[Nx], rs_s[Nx];
    int b  = blockIdx.x >> 7;
    int i0 = (blockIdx.x & 127) << 3;
    for (int t = threadIdx.x; t < Nx; t += 256) {
        sjr_s[t] = g_sRj[b*Nx + t];
        sji_s[t] = g_sIj[b*Nx + t];
        cm_s[t]  = g_cmax[b*Nx + t];
        rs_s[t]  = g_rsum[b*Nx + t];
    }
    __syncthreads();
    int wid = threadIdx.x >> 5, lane = threadIdx.x & 31;
    int i = i0 + wid;
    float sri = g_sRi[b*Nx + i] + br[0];
    float sii = g_sIi[b*Nx + i] + bi[0];
    float apr = par[0], api = pai[0];
    const size_t MS = (size_t)Nx * Nx;
    const float* pR = Lr + (size_t)b * Mx * MS + (size_t)i * Nx;
    const float* pI = Li + (size_t)b * Mx * MS + (size_t)i * Nx;

    float aR[4] = {0.f,0.f,0.f,0.f};
    float aI[4] = {0.f,0.f,0.f,0.f};

#pragma unroll 1
    for (int jb = 0; jb < Nx; jb += 128) {
        int j0 = jb + (lane << 2);
        float4 R0 = __ldcs((const float4*)(pR          + j0));
        float4 R1 = __ldcs((const float4*)(pR +   MS   + j0));
        float4 R2 = __ldcs((const float4*)(pR + 2*MS   + j0));
        float4 R3 = __ldcs((const float4*)(pR + 3*MS   + j0));
        float4 I0 = __ldcs((const float4*)(pI          + j0));
        float4 I1 = __ldcs((const float4*)(pI +   MS   + j0));
        float4 I2 = __ldcs((const float4*)(pI + 2*MS   + j0));
        float4 I3 = __ldcs((const float4*)(pI + 3*MS   + j0));
        float4 vjr = *(const float4*)&sjr_s[j0];
        float4 vji = *(const float4*)&sji_s[j0];
        float4 vcm = *(const float4*)&cm_s[j0];
        float4 vrs = *(const float4*)&rs_s[j0];

        float ar[4], ai[4];
        const float* jr = (const float*)&vjr;
        const float* ji = (const float*)&vji;
        const float* cm = (const float*)&vcm;
        const float* rs = (const float*)&vrs;
#pragma unroll
        for (int q = 0; q < 4; q++) {
            float scr = sri + jr[q];
            float sci = sii + ji[q];
            float pr = scr >= 0.f ? scr : apr * scr;
            float pi = sci >= 0.f ? sci : api * sci;
            float s2 = fmaf(pr, pr, pi * pi);
            float rm = rsqrtf(fmaxf(s2, 1e-36f));
            float mg = s2 * rm;
            float sc = __fdividef(__expf(mg - cm[q]) * rs[q], mg + 1e-12f);
            ar[q] = sc * pr;
            ai[q] = sc * pi;
        }
        const float* r0 = (const float*)&R0; const float* i0p = (const float*)&I0;
        const float* r1 = (const float*)&R1; const float* i1p = (const float*)&I1;
        const float* r2 = (const float*)&R2; const float* i2p = (const float*)&I2;
        const float* r3 = (const float*)&R3; const float* i3p = (const float*)&I3;
#pragma unroll
        for (int q = 0; q < 4; q++) {
            aR[0] = fmaf(r0[q], ar[q], fmaf(i0p[q], -ai[q], aR[0]));
            aI[0] = fmaf(r0[q], ai[q], fmaf(i0p[q],  ar[q], aI[0]));
            aR[1] = fmaf(r1[q], ar[q], fmaf(i1p[q], -ai[q], aR[1]));
            aI[1] = fmaf(r1[q], ai[q], fmaf(i1p[q],  ar[q], aI[1]));
            aR[2] = fmaf(r2[q], ar[q], fmaf(i2p[q], -ai[q], aR[2]));
            aI[2] = fmaf(r2[q], ai[q], fmaf(i2p[q],  ar[q], aI[2]));
            aR[3] = fmaf(r3[q], ar[q], fmaf(i3p[q], -ai[q], aR[3]));
            aI[3] = fmaf(r3[q], ai[q], fmaf(i3p[q],  ar[q], aI[3]));
        }
    }
#pragma unroll
    for (int off = 16; off; off >>= 1) {
#pragma unroll
        for (int m = 0; m < 4; m++) {
            aR[m] += __shfl_xor_sync(0xffffffffu, aR[m], off);
            aI[m] += __shfl_xor_sync(0xffffffffu, aI[m], off);
        }
    }
    if (lane == 0) {
        size_t o = (size_t)b * Mx * Nx + i;
#pragma unroll
        for (int m = 0; m < 4; m++) {
            g_rowR[o + m*Nx] = aR[m];
            g_rowI[o + m*Nx] = aI[m];
        }
    }
}

// ---------------- kernel D v8: m-split GEMM, 8x4 thread tiles ---------------
// grid 512 = 4 m x 128 row-tiles. Block: 128 threads, 64 rows x 64 outs.
// Thread tile 8 rows x 4 outs: 64 FMA per 6 LDS.128 -> 1.5 B/FMA
// (LDS floor ~12us < FMA floor ~16us, so FMA is the single binding pipe).
// smem 69.6KB -> 3 blocks/SM, ~12 warps/SM.
__global__ void __launch_bounds__(128) kD(const float* __restrict__ Xr,
                                          const float* __restrict__ Xi,
                                          const float* __restrict__ wr,
                                          const float* __restrict__ wi)
{
    extern __shared__ __align__(16) float sm[];
    float* Xr_s = sm;                    // [64][68]  (c-major, 64 rows + pad)
    float* Xi_s = sm + 64*68;            // [64][68]
    float* wr_s = sm + 2*64*68;          // [64][68]
    float* wi_s = sm + 3*64*68;          // [64][68]

    int tid  = threadIdx.x;
    int m    = blockIdx.x & 3;
    int tile = blockIdx.x >> 2;
    int r0 = tile << 6;                  // 64 rows per block
    int b  = r0 >> 10;
    int jbase = r0 & 1023;

    // stage X tile transposed: 1024 (row, cgroup) float4 tasks per tensor
#pragma unroll
    for (int it = 0; it < 8; it++) {
        int idx = tid + (it << 7);       // 0..1023
        int r  = idx >> 4;               // 0..63
        int cg = (idx & 15) << 2;        // 0..60
        float4 v = __ldg((const float4*)(Xr + (size_t)(r0 + r)*64 + cg));
        Xr_s[(cg+0)*68 + r] = v.x;
        Xr_s[(cg+1)*68 + r] = v.y;
        Xr_s[(cg+2)*68 + r] = v.z;
        Xr_s[(cg+3)*68 + r] = v.w;
        float4 u = __ldg((const float4*)(Xi + (size_t)(r0 + r)*64 + cg));
        Xi_s[(cg+0)*68 + r] = u.x;
        Xi_s[(cg+1)*68 + r] = u.y;
        Xi_s[(cg+2)*68 + r] = u.z;
        Xi_s[(cg+3)*68 + r] = u.w;
    }
    // stage this m's weights [c][o]
    {
        const float4* wrg = (const float4*)(wr + (size_t)m * 4096);
        const float4* wig = (const float4*)(wi + (size_t)m * 4096);
#pragma unroll
        for (int k = 0; k < 8; k++) {
            int idx = tid + (k << 7);          // 0..1023
            int c = idx >> 4, og = (idx & 15) << 2;
            *(float4*)&wr_s[c*68 + og] = __ldg(wrg + idx);
            *(float4*)&wi_s[c*68 + og] = __ldg(wig + idx);
        }
    }
    __syncthreads();

    int tx = tid & 15, ty = tid >> 4;    // tx: out-group (16), ty: row-group (8)
    int oo = tx << 2;                    // outputs oo..oo+3
    int rr = ty << 3;                    // rows rr..rr+7

    float pR[8][4], pI[8][4];
#pragma unroll
    for (int r = 0; r < 8; r++)
#pragma unroll
        for (int o = 0; o < 4; o++) { pR[r][o] = 0.f; pI[r][o] = 0.f; }

#pragma unroll 4
    for (int c = 0; c < 64; c++) {
        float4 xa0 = *(const float4*)&Xr_s[c*68 + rr];
        float4 xa1 = *(const float4*)&Xr_s[c*68 + rr + 4];
        float4 ya0 = *(const float4*)&Xi_s[c*68 + rr];
        float4 ya1 = *(const float4*)&Xi_s[c*68 + rr + 4];
        float4 wv  = *(const float4*)&wr_s[c*68 + oo];
        float4 vv  = *(const float4*)&wi_s[c*68 + oo];
        float xa[8] = {xa0.x, xa0.y, xa0.z, xa0.w, xa1.x, xa1.y, xa1.z, xa1.w};
        float ya[8] = {ya0.x, ya0.y, ya0.z, ya0.w, ya1.x, ya1.y, ya1.z, ya1.w};
        float wa[4] = {wv.x,  wv.y,  wv.z,  wv.w};
        float va[4] = {vv.x,  vv.y,  vv.z,  vv.w};
#pragma unroll
        for (int r = 0; r < 8; r++)
#pragma unroll
            for (int o = 0; o < 4; o++) {
                pR[r][o] = fmaf(xa[r], wa[o], pR[r][o]);
                pI[r][o] = fmaf(ya[r], va[o], pI[r][o]);
            }
    }

    // epilogue: combine with rowR/rowI and store coalesced per-m partials
    float* gR = g_pR + (size_t)m * BNO;
    float* gI = g_pI + (size_t)m * BNO;
#pragma unroll
    for (int r = 0; r < 8; r++) {
        size_t o = (size_t)(b*Mx + m)*Nx + jbase + rr + r;
        float cRr = __ldg(&g_rowR[o]);
        float cIr = __ldg(&g_rowI[o]);
        size_t idx = (size_t)(r0 + rr + r) * 64 + oo;
        float4 vr, vi;
        vr.x = fmaf(cRr, pR[r][0], -cIr * pI[r][0]);
        vr.y = fmaf(cRr, pR[r][1], -cIr * pI[r][1]);
        vr.z = fmaf(cRr, pR[r][2], -cIr * pI[r][2]);
        vr.w = fmaf(cRr, pR[r][3], -cIr * pI[r][3]);
        vi.x = fmaf(cIr, pR[r][0],  cRr * pI[r][0]);
        vi.y = fmaf(cIr, pR[r][1],  cRr * pI[r][1]);
        vi.z = fmaf(cIr, pR[r][2],  cRr * pI[r][2]);
        vi.w = fmaf(cIr, pR[r][3],  cRr * pI[r][3]);
        *(float4*)(gR + idx) = vr;
        *(float4*)(gI + idx) = vi;
    }
}

// ---------------- kernel E: combine 4 m-partials into out -------------------
__global__ void __launch_bounds__(256) kE(float* __restrict__ out)
{
    size_t idx = ((size_t)blockIdx.x * 256 + threadIdx.x) << 2;   // x4 floats
    float4 r0 = *(const float4*)&g_pR[idx];
    float4 r1 = *(const float4*)&g_pR[(size_t)BNO + idx];
    float4 r2 = *(const float4*)&g_pR[(size_t)2*BNO + idx];
    float4 r3 = *(const float4*)&g_pR[(size_t)3*BNO + idx];
    float4 i0 = *(const float4*)&g_pI[idx];
    float4 i1 = *(const float4*)&g_pI[(size_t)BNO + idx];
    float4 i2 = *(const float4*)&g_pI[(size_t)2*BNO + idx];
    float4 i3 = *(const float4*)&g_pI[(size_t)3*BNO + idx];
    float4 vr, vi;
    vr.x = (r0.x + r1.x) + (r2.x + r3.x);
    vr.y = (r0.y + r1.y) + (r2.y + r3.y);
    vr.z = (r0.z + r1.z) + (r2.z + r3.z);
    vr.w = (r0.w + r1.w) + (r2.w + r3.w);
    vi.x = (i0.x + i1.x) + (i2.x + i3.x);
    vi.y = (i0.y + i1.y) + (i2.y + i3.y);
    vi.z = (i0.z + i1.z) + (i2.z + i3.z);
    vi.w = (i0.w + i1.w) + (i2.w + i3.w);
    *(float4*)(out + idx)               = vr;
    *(float4*)(out + (size_t)BNO + idx) = vi;
}

// ---------------- launch ----------------------------------------------------
extern "C" void kernel_launch(void* const* d_in, const int* in_sizes, int n_in,
                              void* d_out, int out_size)
{
    const float* Xr  = (const float*)d_in[0];
    const float* Xi  = (const float*)d_in[1];
    const float* Lr  = (const float*)d_in[2];
    const float* Li  = (const float*)d_in[3];
    const float* wr  = (const float*)d_in[4];
    const float* wi  = (const float*)d_in[5];
    const float* awr = (const float*)d_in[6];
    const float* awi = (const float*)d_in[7];
    const float* abr = (const float*)d_in[8];
    const float* abi = (const float*)d_in[9];
    const float* par = (const float*)d_in[10];
    const float* pai = (const float*)d_in[11];
    float* out = (float*)d_out;

    const int KD_SMEM = (4*64*68) * 4;   // 69632 bytes
    static int attr_done = 0;
    if (!attr_done) {
        cudaFuncSetAttribute(kD, cudaFuncAttributeMaxDynamicSharedMemorySize, KD_SMEM);
        attr_done = 1;
    }

    kA<<<BN/8, 256>>>(Xr, Xi, awr, awi);
    kB<<<Bx*256, 256>>>(abr, abi, par, pai);
    kC<<<Bx*128, 256>>>(Lr, Li, abr, abi, par, pai);
    kD<<<(BN/64)*4, 128, KD_SMEM>>>(Xr, Xi, wr, wi);
    kE<<<BNO/1024, 256>>>(out);
}

// round 11
// speedup vs baseline: 1.1971x; 1.0183x over previous
#include <cuda_runtime.h>
#include <math.h>

#define Bx 8
#define Nx 1024
#define Cx 64
#define Ox 64
#define Mx 4                 // K+1
#define BN (Bx*Nx)           // 8192
#define BNO (BN*Ox)          // 524288

// ---------------- scratch (device globals; no allocations allowed) ----------
__device__ float g_sRi[BN], g_sIi[BN], g_sRj[BN], g_sIj[BN];
__device__ float g_cmax[BN], g_rsum[BN];
__device__ float g_rowR[Bx*Mx*Nx], g_rowI[Bx*Mx*Nx];
__device__ float g_pR[(size_t)Mx*BNO], g_pI[(size_t)Mx*BNO];   // GEMM partials [m][idx]

// ---------------- kernel A: attention projections ---------------------------
__global__ void __launch_bounds__(256) kA(const float* __restrict__ Xr,
                                          const float* __restrict__ Xi,
                                          const float* __restrict__ awr,
                                          const float* __restrict__ awi)
{
    int gw   = (blockIdx.x * blockDim.x + threadIdx.x) >> 5;
    int lane = threadIdx.x & 31;
    if (gw >= BN) return;
    const float* xr = Xr + (size_t)gw * Cx;
    const float* xi = Xi + (size_t)gw * Cx;
    float a1=0.f,a2=0.f,a3=0.f,a4=0.f,a5=0.f,a6=0.f,a7=0.f,a8=0.f;
#pragma unroll
    for (int k = 0; k < 2; k++) {
        int c = lane + (k << 5);
        float xrv = xr[c], xiv = xi[c];
        float wri = awr[c],      wii = awi[c];
        float wrj = awr[Cx + c], wij = awi[Cx + c];
        a1 = fmaf(xrv, wri, a1);  a2 = fmaf(xiv, wii, a2);
        a3 = fmaf(xrv, wii, a3);  a4 = fmaf(xiv, wri, a4);
        a5 = fmaf(xrv, wrj, a5);  a6 = fmaf(xiv, wij, a6);
        a7 = fmaf(xrv, wij, a7);  a8 = fmaf(xiv, wrj, a8);
    }
#pragma unroll
    for (int off = 16; off; off >>= 1) {
        a1 += __shfl_xor_sync(0xffffffffu, a1, off);
        a2 += __shfl_xor_sync(0xffffffffu, a2, off);
        a3 += __shfl_xor_sync(0xffffffffu, a3, off);
        a4 += __shfl_xor_sync(0xffffffffu, a4, off);
        a5 += __shfl_xor_sync(0xffffffffu, a5, off);
        a6 += __shfl_xor_sync(0xffffffffu, a6, off);
        a7 += __shfl_xor_sync(0xffffffffu, a7, off);
        a8 += __shfl_xor_sync(0xffffffffu, a8, off);
    }
    if (lane == 0) {
        g_sRi[gw] = a1 - a2;
        g_sIi[gw] = a3 + a4;
        g_sRj[gw] = a5 - a6;
        g_sIj[gw] = a7 + a8;
    }
}

// ---------------- kernel B: per-(b,j) softmax stats over i ------------------
__global__ void __launch_bounds__(256) kB(const float* __restrict__ br,
                                          const float* __restrict__ bi,
                                          const float* __restrict__ par,
                                          const float* __restrict__ pai)
{
    __shared__ float sri_s[Nx], sii_s[Nx];
    __shared__ float red[8];
    int b  = blockIdx.x >> 8;
    int j0 = (blockIdx.x & 255) << 2;
    float biasr = br[0], biasi = bi[0];
    float apr = par[0], api = pai[0];
    for (int t = threadIdx.x; t < Nx; t += 256) {
        sri_s[t] = g_sRi[b*Nx + t] + biasr;
        sii_s[t] = g_sIi[b*Nx + t] + biasi;
    }
    __syncthreads();
    int lane = threadIdx.x & 31, wid = threadIdx.x >> 5;
    for (int jj = 0; jj < 4; jj++) {
        int j = j0 + jj;
        float sjr = g_sRj[b*Nx + j];
        float sji = g_sIj[b*Nx + j];
        float mags[4];
        float lmax = -1e30f;
#pragma unroll
        for (int k = 0; k < 4; k++) {
            int i = threadIdx.x + (k << 8);
            float scr = sri_s[i] + sjr;
            float sci = sii_s[i] + sji;
            float pr = scr >= 0.f ? scr : apr * scr;
            float pi = sci >= 0.f ? sci : api * sci;
            float s2 = fmaf(pr, pr, pi * pi);
            float rm = rsqrtf(fmaxf(s2, 1e-36f));
            float mg = s2 * rm;
            mags[k] = mg;
            lmax = fmaxf(lmax, mg);
        }
#pragma unroll
        for (int off = 16; off; off >>= 1)
            lmax = fmaxf(lmax, __shfl_xor_sync(0xffffffffu, lmax, off));
        if (lane == 0) red[wid] = lmax;
        __syncthreads();
        float M = red[0];
#pragma unroll
        for (int t = 1; t < 8; t++) M = fmaxf(M, red[t]);
        __syncthreads();
        float ls = 0.f;
#pragma unroll
        for (int k = 0; k < 4; k++) ls += __expf(mags[k] - M);
#pragma unroll
        for (int off = 16; off; off >>= 1)
            ls += __shfl_xor_sync(0xffffffffu, ls, off);
        if (lane == 0) red[wid] = ls;
        __syncthreads();
        if (threadIdx.x == 0) {
            float S = red[0]+red[1]+red[2]+red[3]+red[4]+red[5]+red[6]+red[7];
            g_cmax[b*Nx + j] = M;
            g_rsum[b*Nx + j] = 1.0f / S;
        }
        __syncthreads();
    }
}

// ---------------- kernel C v2 (measured best): 128-j chunks, 8 LDG.128 ------
__global__ void __launch_bounds__(256) kC(const float* __restrict__ Lr,
                                          const float* __restrict__ Li,
                                          const float* __restrict__ br,
                                          const float* __restrict__ bi,
                                          const float* __restrict__ par,
                                          const float* __restrict__ pai)
{
    __shared__ float sjr_s[Nx], sji_s[Nx], cm_s[Nx], rs_s[Nx];
    int b  = blockIdx.x >> 7;
    int i0 = (blockIdx.x & 127) << 3;
    for (int t = threadIdx.x; t < Nx; t += 256) {
        sjr_s[t] = g_sRj[b*Nx + t];
        sji_s[t] = g_sIj[b*Nx + t];
        cm_s[t]  = g_cmax[b*Nx + t];
        rs_s[t]  = g_rsum[b*Nx + t];
    }
    __syncthreads();
    int wid = threadIdx.x >> 5, lane = threadIdx.x & 31;
    int i = i0 + wid;
    float sri = g_sRi[b*Nx + i] + br[0];
    float sii = g_sIi[b*Nx + i] + bi[0];
    float apr = par[0], api = pai[0];
    const size_t MS = (size_t)Nx * Nx;
    const float* pR = Lr + (size_t)b * Mx * MS + (size_t)i * Nx;
    const float* pI = Li + (size_t)b * Mx * MS + (size_t)i * Nx;

    float aR[4] = {0.f,0.f,0.f,0.f};
    float aI[4] = {0.f,0.f,0.f,0.f};

#pragma unroll 1
    for (int jb = 0; jb < Nx; jb += 128) {
        int j0 = jb + (lane << 2);
        float4 R0 = __ldcs((const float4*)(pR          + j0));
        float4 R1 = __ldcs((const float4*)(pR +   MS   + j0));
        float4 R2 = __ldcs((const float4*)(pR + 2*MS   + j0));
        float4 R3 = __ldcs((const float4*)(pR + 3*MS   + j0));
        float4 I0 = __ldcs((const float4*)(pI          + j0));
        float4 I1 = __ldcs((const float4*)(pI +   MS   + j0));
        float4 I2 = __ldcs((const float4*)(pI + 2*MS   + j0));
        float4 I3 = __ldcs((const float4*)(pI + 3*MS   + j0));
        float4 vjr = *(const float4*)&sjr_s[j0];
        float4 vji = *(const float4*)&sji_s[j0];
        float4 vcm = *(const float4*)&cm_s[j0];
        float4 vrs = *(const float4*)&rs_s[j0];

        float ar[4], ai[4];
        const float* jr = (const float*)&vjr;
        const float* ji = (const float*)&vji;
        const float* cm = (const float*)&vcm;
        const float* rs = (const float*)&vrs;
#pragma unroll
        for (int q = 0; q < 4; q++) {
            float scr = sri + jr[q];
            float sci = sii + ji[q];
            float pr = scr >= 0.f ? scr : apr * scr;
            float pi = sci >= 0.f ? sci : api * sci;
            float s2 = fmaf(pr, pr, pi * pi);
            float rm = rsqrtf(fmaxf(s2, 1e-36f));
            float mg = s2 * rm;
            float sc = __fdividef(__expf(mg - cm[q]) * rs[q], mg + 1e-12f);
            ar[q] = sc * pr;
            ai[q] = sc * pi;
        }
        const float* r0 = (const float*)&R0; const float* i0p = (const float*)&I0;
        const float* r1 = (const float*)&R1; const float* i1p = (const float*)&I1;
        const float* r2 = (const float*)&R2; const float* i2p = (const float*)&I2;
        const float* r3 = (const float*)&R3; const float* i3p = (const float*)&I3;
#pragma unroll
        for (int q = 0; q < 4; q++) {
            aR[0] = fmaf(r0[q], ar[q], fmaf(i0p[q], -ai[q], aR[0]));
            aI[0] = fmaf(r0[q], ai[q], fmaf(i0p[q],  ar[q], aI[0]));
            aR[1] = fmaf(r1[q], ar[q], fmaf(i1p[q], -ai[q], aR[1]));
            aI[1] = fmaf(r1[q], ai[q], fmaf(i1p[q],  ar[q], aI[1]));
            aR[2] = fmaf(r2[q], ar[q], fmaf(i2p[q], -ai[q], aR[2]));
            aI[2] = fmaf(r2[q], ai[q], fmaf(i2p[q],  ar[q], aI[2]));
            aR[3] = fmaf(r3[q], ar[q], fmaf(i3p[q], -ai[q], aR[3]));
            aI[3] = fmaf(r3[q], ai[q], fmaf(i3p[q],  ar[q], aI[3]));
        }
    }
#pragma unroll
    for (int off = 16; off; off >>= 1) {
#pragma unroll
        for (int m = 0; m < 4; m++) {
            aR[m] += __shfl_xor_sync(0xffffffffu, aR[m], off);
            aI[m] += __shfl_xor_sync(0xffffffffu, aI[m], off);
        }
    }
    if (lane == 0) {
        size_t o = (size_t)b * Mx * Nx + i;
#pragma unroll
        for (int m = 0; m < 4; m++) {
            g_rowR[o + m*Nx] = aR[m];
            g_rowI[o + m*Nx] = aI[m];
        }
    }
}

// ---------------- kernel G: pure X@W GEMM partials (independent branch) -----
// grid 512 = 4 m x 128 row-tiles. Block: 128 threads, 64 rows x 64 outs,
// 8x4 thread tiles. Writes raw P_r/P_i partials [m][idx] (no rowR combine).
__global__ void __launch_bounds__(128) kG(const float* __restrict__ Xr,
                                          const float* __restrict__ Xi,
                                          const float* __restrict__ wr,
                                          const float* __restrict__ wi)
{
    extern __shared__ __align__(16) float sm[];
    float* Xr_s = sm;                    // [64][68]
    float* Xi_s = sm + 64*68;            // [64][68]
    float* wr_s = sm + 2*64*68;          // [64][68]
    float* wi_s = sm + 3*64*68;          // [64][68]

    int tid  = threadIdx.x;
    int m    = blockIdx.x & 3;
    int tile = blockIdx.x >> 2;
    int r0 = tile << 6;                  // 64 rows per block

#pragma unroll
    for (int it = 0; it < 8; it++) {
        int idx = tid + (it << 7);       // 0..1023
        int r  = idx >> 4;               // 0..63
        int cg = (idx & 15) << 2;        // 0..60
        float4 v = __ldg((const float4*)(Xr + (size_t)(r0 + r)*64 + cg));
        Xr_s[(cg+0)*68 + r] = v.x;
        Xr_s[(cg+1)*68 + r] = v.y;
        Xr_s[(cg+2)*68 + r] = v.z;
        Xr_s[(cg+3)*68 + r] = v.w;
        float4 u = __ldg((const float4*)(Xi + (size_t)(r0 + r)*64 + cg));
        Xi_s[(cg+0)*68 + r] = u.x;
        Xi_s[(cg+1)*68 + r] = u.y;
        Xi_s[(cg+2)*68 + r] = u.z;
        Xi_s[(cg+3)*68 + r] = u.w;
    }
    {
        const float4* wrg = (const float4*)(wr + (size_t)m * 4096);
        const float4* wig = (const float4*)(wi + (size_t)m * 4096);
#pragma unroll
        for (int k = 0; k < 8; k++) {
            int idx = tid + (k << 7);          // 0..1023
            int c = idx >> 4, og = (idx & 15) << 2;
            *(float4*)&wr_s[c*68 + og] = __ldg(wrg + idx);
            *(float4*)&wi_s[c*68 + og] = __ldg(wig + idx);
        }
    }
    __syncthreads();

    int tx = tid & 15, ty = tid >> 4;    // tx: out-group (16), ty: row-group (8)
    int oo = tx << 2;
    int rr = ty << 3;

    float pR[8][4], pI[8][4];
#pragma unroll
    for (int r = 0; r < 8; r++)
#pragma unroll
        for (int o = 0; o < 4; o++) { pR[r][o] = 0.f; pI[r][o] = 0.f; }

#pragma unroll 4
    for (int c = 0; c < 64; c++) {
        float4 xa0 = *(const float4*)&Xr_s[c*68 + rr];
        float4 xa1 = *(const float4*)&Xr_s[c*68 + rr + 4];
        float4 ya0 = *(const float4*)&Xi_s[c*68 + rr];
        float4 ya1 = *(const float4*)&Xi_s[c*68 + rr + 4];
        float4 wv  = *(const float4*)&wr_s[c*68 + oo];
        float4 vv  = *(const float4*)&wi_s[c*68 + oo];
        float xa[8] = {xa0.x, xa0.y, xa0.z, xa0.w, xa1.x, xa1.y, xa1.z, xa1.w};
        float ya[8] = {ya0.x, ya0.y, ya0.z, ya0.w, ya1.x, ya1.y, ya1.z, ya1.w};
        float wa[4] = {wv.x,  wv.y,  wv.z,  wv.w};
        float va[4] = {vv.x,  vv.y,  vv.z,  vv.w};
#pragma unroll
        for (int r = 0; r < 8; r++)
#pragma unroll
            for (int o = 0; o < 4; o++) {
                pR[r][o] = fmaf(xa[r], wa[o], pR[r][o]);
                pI[r][o] = fmaf(ya[r], va[o], pI[r][o]);
            }
    }

    float* gR = g_pR + (size_t)m * BNO;
    float* gI = g_pI + (size_t)m * BNO;
#pragma unroll
    for (int r = 0; r < 8; r++) {
        size_t idx = (size_t)(r0 + rr + r) * 64 + oo;
        *(float4*)(gR + idx) = make_float4(pR[r][0], pR[r][1], pR[r][2], pR[r][3]);
        *(float4*)(gI + idx) = make_float4(pI[r][0], pI[r][1], pI[r][2], pI[r][3]);
    }
}

// ---------------- kernel F: epilogue — combine rowR/rowI with P, sum m ------
__global__ void __launch_bounds__(256) kF(float* __restrict__ out)
{
    size_t t   = (size_t)blockIdx.x * 256 + threadIdx.x;
    size_t idx = t << 2;                 // 4 consecutive outputs (same row)
    int row = (int)(idx >> 6);           // global row
    int b = row >> 10, j = row & 1023;

    float4 accR = make_float4(0.f,0.f,0.f,0.f);
    float4 accI = make_float4(0.f,0.f,0.f,0.f);
#pragma unroll
    for (int m = 0; m < Mx; m++) {
        float cR = __ldg(&g_rowR[(size_t)(b*Mx + m)*Nx + j]);
        float cI = __ldg(&g_rowI[(size_t)(b*Mx + m)*Nx + j]);
        float4 pr = *(const float4*)&g_pR[(size_t)m*BNO + idx];
        float4 pi = *(const float4*)&g_pI[(size_t)m*BNO + idx];
        accR.x = fmaf(cR, pr.x, fmaf(-cI, pi.x, accR.x));
        accR.y = fmaf(cR, pr.y, fmaf(-cI, pi.y, accR.y));
        accR.z = fmaf(cR, pr.z, fmaf(-cI, pi.z, accR.z));
        accR.w = fmaf(cR, pr.w, fmaf(-cI, pi.w, accR.w));
        accI.x = fmaf(cI, pr.x, fmaf( cR, pi.x, accI.x));
        accI.y = fmaf(cI, pr.y, fmaf( cR, pi.y, accI.y));
        accI.z = fmaf(cI, pr.z, fmaf( cR, pi.z, accI.z));
        accI.w = fmaf(cI, pr.w, fmaf( cR, pi.w, accI.w));
    }
    *(float4*)(out + idx)               = accR;
    *(float4*)(out + (size_t)BNO + idx) = accI;
}

// ---------------- launch: fork kG onto a side stream, join before kF --------
extern "C" void kernel_launch(void* const* d_in, const int* in_sizes, int n_in,
                              void* d_out, int out_size)
{
    const float* Xr  = (const float*)d_in[0];
    const float* Xi  = (const float*)d_in[1];
    const float* Lr  = (const float*)d_in[2];
    const float* Li  = (const float*)d_in[3];
    const float* wr  = (const float*)d_in[4];
    const float* wi  = (const float*)d_in[5];
    const float* awr = (const float*)d_in[6];
    const float* awi = (const float*)d_in[7];
    const float* abr = (const float*)d_in[8];
    const float* abi = (const float*)d_in[9];
    const float* par = (const float*)d_in[10];
    const float* pai = (const float*)d_in[11];
    float* out = (float*)d_out;

    const int KG_SMEM = (4*64*68) * 4;   // 69632 bytes

    static cudaStream_t s2 = nullptr;
    static cudaEvent_t  eFork = nullptr, eJoin = nullptr;
    if (!s2) {
        cudaFuncSetAttribute(kG, cudaFuncAttributeMaxDynamicSharedMemorySize, KG_SMEM);
        cudaStreamCreateWithFlags(&s2, cudaStreamNonBlocking);
        cudaEventCreateWithFlags(&eFork, cudaEventDisableTiming);
        cudaEventCreateWithFlags(&eJoin, cudaEventDisableTiming);
    }

    // fork: kG (pure GEMM, independent of everything) on side stream
    cudaEventRecord(eFork, 0);
    cudaStreamWaitEvent(s2, eFork, 0);
    kG<<<(BN/64)*4, 128, KG_SMEM, s2>>>(Xr, Xi, wr, wi);

    // main chain: attention stats + the 268MB L reduction
    kA<<<BN/8, 256>>>(Xr, Xi, awr, awi);
    kB<<<Bx*256, 256>>>(abr, abi, par, pai);
    kC<<<Bx*128, 256>>>(Lr, Li, abr, abi, par, pai);

    // join: epilogue needs both rowR/rowI (kC) and P partials (kG)
    cudaEventRecord(eJoin, s2);
    cudaStreamWaitEvent(0, eJoin, 0);
    kF<<<BNO/1024, 256>>>(out);
}